// round 7
// baseline (speedup 1.0000x reference)
#include <cuda_runtime.h>

// Shapes (fixed for this problem)
#define B_  2
#define T_  2048
#define H_  8
#define D_  64
#define M_  64
#define C_  32                 // chunk length (timesteps per block)
#define NC_ (T_ / C_)          // 64 chunks per (b,h)
#define RS  512                // row stride in floats between consecutive t (H*D)
#define PAD 68                 // smem row stride in floats (272B, 16B-aligned)
#define PAD4 (PAD / 4)         // 17 float4s per row
#define NSEG 4                 // time segments per chunk (8 steps each)

// Per-(b,h,chunk) column sums of fmap(k): [B*H*NC][D]
__device__ float g_chunksum[B_ * H_ * NC_ * D_];

__device__ __forceinline__ float fmap(float x) {
    // elu(x) + 1 (alpha=1): x>0 -> x+1 ; x<=0 -> exp(x)
    return x > 0.0f ? x + 1.0f : __expf(x);
}
__device__ __forceinline__ float4 fmap4(float4 a) {
    return make_float4(fmap(a.x), fmap(a.y), fmap(a.z), fmap(a.w));
}
__device__ __forceinline__ float4 add4(float4 a, float4 b) {
    return make_float4(a.x + b.x, a.y + b.y, a.z + b.z, a.w + b.w);
}

// ---------------------------------------------------------------------------
// Kernel 1: per-chunk (32 steps) column sums of fmap(k). grid = 1024, 256 thr.
// ---------------------------------------------------------------------------
__global__ __launch_bounds__(256) void k_chunksum(const float* __restrict__ k) {
    __shared__ float4 red[16][16];          // [tg][dv]
    const int bc  = blockIdx.x;
    const int c   = bc & (NC_ - 1);
    const int bh  = bc >> 6;
    const int h   = bh & (H_ - 1);
    const int b   = bh >> 3;
    const int tid = threadIdx.x;
    const int tg  = tid >> 4;
    const int dv  = tid & 15;

    const size_t base = (((size_t)b * T_ + (size_t)c * C_) * H_ + h) * D_;

    float4 s = make_float4(0.f, 0.f, 0.f, 0.f);
    #pragma unroll
    for (int i = 0; i < 2; i++) {
        const int t = tg + i * 16;
        s = add4(s, fmap4(*(const float4*)(k + base + (size_t)t * RS + dv * 4)));
    }
    red[tg][dv] = s;
    __syncthreads();

    if (tid < 16) {
        float4 acc = red[0][tid];
        #pragma unroll
        for (int t = 1; t < 16; t++) acc = add4(acc, red[t][tid]);
        *(float4*)(&g_chunksum[bc * D_ + tid * 4]) = acc;
    }
}

// ---------------------------------------------------------------------------
// Kernel 2: main. grid = 1024 blocks, 256 threads, smem ~11KB, 3 barriers.
// Only the time-scan of fmap(k) lives in smem; q,v flow through registers.
// ---------------------------------------------------------------------------
__global__ __launch_bounds__(256) void k_main(const float* __restrict__ q,
                                              const float* __restrict__ k,
                                              const float* __restrict__ v,
                                              float* __restrict__ out) {
    __shared__ float loc_s[C_ * PAD];      // fmap(k) -> local inclusive time-scan (in place)
    __shared__ float segsum[NSEG * 64];    // per-segment column sums
    __shared__ float carp[4 * 64];         // carry partials (4-way split over prior chunks)
    __shared__ float carr[64];             // cross-chunk carry per d

    float4* loc4 = (float4*)loc_s;
    float4* ca4  = (float4*)carr;

    const int bc  = blockIdx.x;
    const int c   = bc & (NC_ - 1);
    const int bh  = bc >> 6;
    const int h   = bh & (H_ - 1);
    const int b   = bh >> 3;
    const int tid = threadIdx.x;

    const size_t base = (((size_t)b * T_ + (size_t)c * C_) * H_ + h) * D_;

    // ---- Carry partials: 256 threads, 4-way chunk split (independent LDGs) ----
    {
        const int d = tid & 63, p = tid >> 6;
        const int lo = p * 16;
        const int hi = (c < lo + 16) ? c : (lo + 16);
        float run = 0.0f;
        const float* cs = &g_chunksum[(bh << 6) * D_ + d];
        #pragma unroll 4
        for (int cc = lo; cc < hi; cc++) run += cs[cc * D_];
        carp[p * 64 + d] = run;
    }

    // ---- Phase A: coalesced vector load of k -> fmap -> smem (STS.128) ----
    #pragma unroll
    for (int it = 0; it < 2; it++) {
        const int i  = tid + it * 256;         // 0..511
        const int t  = i >> 4;
        const int dv = i & 15;
        loc4[t * PAD4 + dv] = fmap4(*(const float4*)(k + base + (size_t)t * RS + dv * 4));
    }
    __syncthreads();

    // ---- B1: local inclusive time-scan IN PLACE (256 threads = 64 d x 4 seg) ----
    {
        const int d = tid & 63, seg = tid >> 6;
        float run = 0.0f;
        #pragma unroll
        for (int i = 0; i < C_ / NSEG; i++) {
            const int t = seg * (C_ / NSEG) + i;
            run += loc_s[t * PAD + d];
            loc_s[t * PAD + d] = run;
        }
        segsum[seg * 64 + d] = run;
    }
    __syncthreads();

    // ---- B2 offsets (segs 1..3) || carry reduce (tid<64) ----
    if (tid < 64) {
        carr[tid] = carp[tid] + carp[64 + tid] + carp[128 + tid] + carp[192 + tid];
    } else {
        const int d = tid & 63, seg = tid >> 6;   // 1..3
        float off = segsum[d];
        for (int s = 1; s < seg; s++) off += segsum[s * 64 + d];
        #pragma unroll
        for (int i = 0; i < C_ / NSEG; i++) {
            const int t = seg * (C_ / NSEG) + i;
            loc_s[t * PAD + d] += off;
        }
    }
    __syncthreads();

    // ---- Phase C: 8 lanes per timestep (t = tid>>3, dgv = tid&7, 8 d's each) ----
    {
        const int t   = tid >> 3;              // 0..31
        const int dgv = tid & 7;               // 0..7
        const size_t rowg = base + (size_t)t * RS + dgv * 8;

        // q (and later v) straight from gmem; issue loads early
        const float4 qr0 = *(const float4*)(q + rowg);
        const float4 qr1 = *(const float4*)(q + rowg + 4);
        const float4 vv0 = *(const float4*)(v + rowg);
        const float4 vv1 = *(const float4*)(v + rowg + 4);

        const int b4 = t * PAD4 + dgv * 2;
        float dcum = 0.0f, S = 0.0f, den = 0.0f, qs = 0.0f;
        #pragma unroll
        for (int j = 0; j < 2; j++) {
            const float4 lv = loc4[b4 + j];
            float4 pv = make_float4(0.f, 0.f, 0.f, 0.f);
            if (t > 0) pv = loc4[b4 - PAD4 + j];
            const float4 qf = (j == 0) ? fmap4(qr0) : fmap4(qr1);
            const float4 cv = ca4[dgv * 2 + j];

            den += qf.x * (lv.x + cv.x) + qf.y * (lv.y + cv.y)
                 + qf.z * (lv.z + cv.z) + qf.w * (lv.w + cv.w);

            dcum += lv.x - pv.x;  S += qf.x * dcum;
            dcum += lv.y - pv.y;  S += qf.y * dcum;
            dcum += lv.z - pv.z;  S += qf.z * dcum;
            dcum += lv.w - pv.w;  S += qf.w * dcum;
            qs   += qf.x + qf.y + qf.z + qf.w;
        }

        // 8-lane exclusive scan of ktot (=dcum) across dgv groups
        const int gl = tid & 7;
        float incl = dcum;
        #pragma unroll
        for (int o = 1; o < 8; o <<= 1) {
            float n = __shfl_up_sync(0xFFFFFFFFu, incl, o);
            if (gl >= o) incl += n;
        }
        const float kpre = incl - dcum;
        S += kpre * qs;

        // butterfly-reduce S and den within the 8-lane group
        #pragma unroll
        for (int o = 4; o > 0; o >>= 1) {
            S   += __shfl_xor_sync(0xFFFFFFFFu, S, o);
            den += __shfl_xor_sync(0xFFFFFFFFu, den, o);
        }
        const float scale = S / den;

        // out = v * scale, straight to gmem
        float4 o0 = vv0, o1 = vv1;
        o0.x *= scale; o0.y *= scale; o0.z *= scale; o0.w *= scale;
        o1.x *= scale; o1.y *= scale; o1.z *= scale; o1.w *= scale;
        *(float4*)(out + rowg)     = o0;
        *(float4*)(out + rowg + 4) = o1;
    }
}

extern "C" void kernel_launch(void* const* d_in, const int* in_sizes, int n_in,
                              void* d_out, int out_size) {
    const float* q = (const float*)d_in[0];
    const float* k = (const float*)d_in[1];
    const float* v = (const float*)d_in[2];
    float* out = (float*)d_out;

    const int nblocks = B_ * H_ * NC_;     // 1024
    k_chunksum<<<nblocks, 256>>>(k);
    k_main<<<nblocks, 256>>>(q, k, v, out);
}

// round 8
// speedup vs baseline: 1.0593x; 1.0593x over previous
#include <cuda_runtime.h>

// Shapes (fixed for this problem)
#define B_  2
#define T_  2048
#define H_  8
#define D_  64
#define M_  64
#define C_  32                 // chunk length (timesteps per block)
#define NC_ (T_ / C_)          // 64 chunks per (b,h)
#define RS  512                // row stride in floats between consecutive t (H*D)
#define PAD 68                 // smem row stride in floats (272B, 16B-aligned)
#define PAD4 (PAD / 4)         // 17 float4s per row
#define NSEG 4                 // time segments per chunk (8 steps each)

// Per-(b,h,chunk) column sums of fmap(k): [B*H*NC][D]
__device__ float g_chunksum[B_ * H_ * NC_ * D_];
// Per-timestep numerator and carry-less denominator: [B*H][T]
__device__ float g_S[B_ * H_ * T_];
__device__ float g_dl[B_ * H_ * T_];

__device__ __forceinline__ float fmap(float x) {
    // elu(x) + 1 (alpha=1): x>0 -> x+1 ; x<=0 -> exp(x)
    return x > 0.0f ? x + 1.0f : __expf(x);
}
__device__ __forceinline__ float4 fmap4(float4 a) {
    return make_float4(fmap(a.x), fmap(a.y), fmap(a.z), fmap(a.w));
}

// ---------------------------------------------------------------------------
// Kernel 1: per-chunk stats. Reads k,q. Emits S[t], den_loc[t], chunksum[d].
// grid = 1024 blocks, 256 threads. q LDGs hoisted above the first barrier.
// ---------------------------------------------------------------------------
__global__ __launch_bounds__(256) void k_stats(const float* __restrict__ k,
                                               const float* __restrict__ q) {
    __shared__ float loc_s[C_ * PAD];      // fmap(k) -> local inclusive time-scan (in place)
    __shared__ float segsum[NSEG * 64];

    float4* loc4 = (float4*)loc_s;

    const int bc  = blockIdx.x;
    const int c   = bc & (NC_ - 1);
    const int bh  = bc >> 6;
    const int h   = bh & (H_ - 1);
    const int b   = bh >> 3;
    const int tid = threadIdx.x;

    const size_t base = (((size_t)b * T_ + (size_t)c * C_) * H_ + h) * D_;

    // ---- Phase A: coalesced k -> fmap -> smem; hoist q LDGs for Phase C ----
    const int t   = tid >> 3;              // 0..31 (Phase C row)
    const int dgv = tid & 7;               // 0..7  (8 d's per lane)
    const size_t rowg = base + (size_t)t * RS + dgv * 8;
    const float4 qr0 = *(const float4*)(q + rowg);       // in flight through scan
    const float4 qr1 = *(const float4*)(q + rowg + 4);

    #pragma unroll
    for (int it = 0; it < 2; it++) {
        const int i  = tid + it * 256;
        const int tt = i >> 4;
        const int dv = i & 15;
        loc4[tt * PAD4 + dv] = fmap4(*(const float4*)(k + base + (size_t)tt * RS + dv * 4));
    }
    __syncthreads();

    // ---- B1: local inclusive time-scan IN PLACE (64 d x 4 seg) ----
    {
        const int d = tid & 63, seg = tid >> 6;
        float run = 0.0f;
        #pragma unroll
        for (int i = 0; i < C_ / NSEG; i++) {
            const int tt = seg * (C_ / NSEG) + i;
            run += loc_s[tt * PAD + d];
            loc_s[tt * PAD + d] = run;
        }
        segsum[seg * 64 + d] = run;
    }
    __syncthreads();

    // ---- B2 offsets (segs 1..3) || chunksum publish (tid<64) ----
    if (tid < 64) {
        g_chunksum[bc * D_ + tid] =
            segsum[tid] + segsum[64 + tid] + segsum[128 + tid] + segsum[192 + tid];
    } else {
        const int d = tid & 63, seg = tid >> 6;   // 1..3
        float off = segsum[d];
        for (int s = 1; s < seg; s++) off += segsum[s * 64 + d];
        #pragma unroll
        for (int i = 0; i < C_ / NSEG; i++) {
            const int tt = seg * (C_ / NSEG) + i;
            loc_s[tt * PAD + d] += off;
        }
    }
    __syncthreads();

    // ---- Phase C: 8 lanes per timestep; q already in registers ----
    {
        const int b4 = t * PAD4 + dgv * 2;
        float dcum = 0.0f, S = 0.0f, den = 0.0f, qs = 0.0f;
        #pragma unroll
        for (int j = 0; j < 2; j++) {
            const float4 lv = loc4[b4 + j];
            float4 pv = make_float4(0.f, 0.f, 0.f, 0.f);
            if (t > 0) pv = loc4[b4 - PAD4 + j];
            const float4 qf = (j == 0) ? fmap4(qr0) : fmap4(qr1);

            den += qf.x * lv.x + qf.y * lv.y + qf.z * lv.z + qf.w * lv.w;

            dcum += lv.x - pv.x;  S += qf.x * dcum;
            dcum += lv.y - pv.y;  S += qf.y * dcum;
            dcum += lv.z - pv.z;  S += qf.z * dcum;
            dcum += lv.w - pv.w;  S += qf.w * dcum;
            qs   += qf.x + qf.y + qf.z + qf.w;
        }

        // 8-lane exclusive scan of per-group ktot across dgv
        float incl = dcum;
        #pragma unroll
        for (int o = 1; o < 8; o <<= 1) {
            float n = __shfl_up_sync(0xFFFFFFFFu, incl, o);
            if (dgv >= o) incl += n;
        }
        S += (incl - dcum) * qs;

        #pragma unroll
        for (int o = 4; o > 0; o >>= 1) {
            S   += __shfl_xor_sync(0xFFFFFFFFu, S, o);
            den += __shfl_xor_sync(0xFFFFFFFFu, den, o);
        }

        if (dgv == 0) {
            const int idx = bh * T_ + c * C_ + t;
            g_S[idx]  = S;
            g_dl[idx] = den;
        }
    }
}

// ---------------------------------------------------------------------------
// Kernel 3: pure streaming output. Reads q,v + tiny stats; writes out.
// No scan, no k, 2 barriers. grid = 1024 blocks, 256 threads.
// ---------------------------------------------------------------------------
__global__ __launch_bounds__(256) void k_out(const float* __restrict__ q,
                                             const float* __restrict__ v,
                                             float* __restrict__ out) {
    __shared__ float carp[4 * 64];         // carry partials
    __shared__ float carr[64];             // cross-chunk carry per d
    float4* ca4 = (float4*)carr;

    const int bc  = blockIdx.x;
    const int c   = bc & (NC_ - 1);
    const int bh  = bc >> 6;
    const int h   = bh & (H_ - 1);
    const int b   = bh >> 3;
    const int tid = threadIdx.x;

    const size_t base = (((size_t)b * T_ + (size_t)c * C_) * H_ + h) * D_;

    // ---- issue all gmem loads up front ----
    const int t   = tid >> 3;
    const int dgv = tid & 7;
    const size_t rowg = base + (size_t)t * RS + dgv * 8;
    const float4 qr0 = *(const float4*)(q + rowg);
    const float4 qr1 = *(const float4*)(q + rowg + 4);
    const float4 vv0 = *(const float4*)(v + rowg);
    const float4 vv1 = *(const float4*)(v + rowg + 4);
    const int idx = bh * T_ + c * C_ + t;
    const float Sv = g_S[idx];
    const float dl = g_dl[idx];

    // ---- carry partials: 4-way chunk split over priors ----
    {
        const int d = tid & 63, p = tid >> 6;
        const int lo = p * 16;
        const int hi = (c < lo + 16) ? c : (lo + 16);
        float run = 0.0f;
        const float* cs = &g_chunksum[(bh << 6) * D_ + d];
        #pragma unroll 4
        for (int cc = lo; cc < hi; cc++) run += cs[cc * D_];
        carp[p * 64 + d] = run;
    }
    __syncthreads();
    if (tid < 64)
        carr[tid] = carp[tid] + carp[64 + tid] + carp[128 + tid] + carp[192 + tid];
    __syncthreads();

    // ---- den = den_loc + qf . carr ; out = v * (S/den) ----
    {
        const float4 qf0 = fmap4(qr0);
        const float4 qf1 = fmap4(qr1);
        const float4 cv0 = ca4[dgv * 2];
        const float4 cv1 = ca4[dgv * 2 + 1];

        float part = qf0.x * cv0.x + qf0.y * cv0.y + qf0.z * cv0.z + qf0.w * cv0.w
                   + qf1.x * cv1.x + qf1.y * cv1.y + qf1.z * cv1.z + qf1.w * cv1.w;
        #pragma unroll
        for (int o = 4; o > 0; o >>= 1)
            part += __shfl_xor_sync(0xFFFFFFFFu, part, o);

        const float scale = Sv / (dl + part);

        float4 o0 = vv0, o1 = vv1;
        o0.x *= scale; o0.y *= scale; o0.z *= scale; o0.w *= scale;
        o1.x *= scale; o1.y *= scale; o1.z *= scale; o1.w *= scale;
        *(float4*)(out + rowg)     = o0;
        *(float4*)(out + rowg + 4) = o1;
    }
}

extern "C" void kernel_launch(void* const* d_in, const int* in_sizes, int n_in,
                              void* d_out, int out_size) {
    const float* q = (const float*)d_in[0];
    const float* k = (const float*)d_in[1];
    const float* v = (const float*)d_in[2];
    float* out = (float*)d_out;

    const int nblocks = B_ * H_ * NC_;     // 1024
    k_stats<<<nblocks, 256>>>(k, q);
    k_out<<<nblocks, 256>>>(q, v, out);
}

// round 10
// speedup vs baseline: 1.0776x; 1.0172x over previous
#include <cuda_runtime.h>

// Shapes (fixed for this problem)
#define B_  2
#define T_  2048
#define H_  8
#define D_  64
#define M_  64
#define CS_ 32                 // chunksum grain (kernel 1)
#define NCS_ (T_ / CS_)        // 64 chunk32s per (b,h)
#define C_  64                 // main-kernel chunk length
#define NC_ (T_ / C_)          // 32 chunks per (b,h)
#define RS  512                // row stride in floats between consecutive t (H*D)
#define PAD 68                 // smem row stride in floats (272B, 16B-aligned)
#define PAD4 (PAD / 4)         // 17 float4s per row
#define NSEG 8                 // time segments per chunk (8 steps each)

// Per-(b,h,chunk32) column sums of fmap(k): [B*H*NCS][D]
__device__ float g_chunksum[B_ * H_ * NCS_ * D_];

__device__ __forceinline__ float fmap(float x) {
    // elu(x) + 1 (alpha=1): x>0 -> x+1 ; x<=0 -> exp(x)
    return x > 0.0f ? x + 1.0f : __expf(x);
}
__device__ __forceinline__ float4 fmap4(float4 a) {
    return make_float4(fmap(a.x), fmap(a.y), fmap(a.z), fmap(a.w));
}
__device__ __forceinline__ float4 add4(float4 a, float4 b) {
    return make_float4(a.x + b.x, a.y + b.y, a.z + b.z, a.w + b.w);
}

// ---------------------------------------------------------------------------
// Kernel 1: per-chunk32 column sums of fmap(k). grid = 1024, 256 thr. (R6 ver)
// ---------------------------------------------------------------------------
__global__ __launch_bounds__(256) void k_chunksum(const float* __restrict__ k) {
    __shared__ float4 red[16][16];          // [tg][dv]
    const int bc  = blockIdx.x;             // bh*64 + c32
    const int c   = bc & (NCS_ - 1);
    const int bh  = bc >> 6;
    const int h   = bh & (H_ - 1);
    const int b   = bh >> 3;
    const int tid = threadIdx.x;
    const int tg  = tid >> 4;
    const int dv  = tid & 15;

    const size_t base = (((size_t)b * T_ + (size_t)c * CS_) * H_ + h) * D_;

    float4 s = make_float4(0.f, 0.f, 0.f, 0.f);
    #pragma unroll
    for (int i = 0; i < 2; i++) {
        const int t = tg + i * 16;
        s = add4(s, fmap4(*(const float4*)(k + base + (size_t)t * RS + dv * 4)));
    }
    red[tg][dv] = s;
    __syncthreads();

    if (tid < 16) {
        float4 acc = red[0][tid];
        #pragma unroll
        for (int t = 1; t < 16; t++) acc = add4(acc, red[t][tid]);
        *(float4*)(&g_chunksum[bc * D_ + tid * 4]) = acc;
    }
}

// ---------------------------------------------------------------------------
// Kernel 2: main. C=64 chunks, grid = 512 blocks x 512 threads.
// 3 blocks/SM (smem 21.7KB, regs<=41) -> ~55 warps/SM despite grid-limited
// block count. Lean R7 phase structure; q hoisted over the scan.
// ---------------------------------------------------------------------------
__global__ __launch_bounds__(512, 3) void k_main(const float* __restrict__ q,
                                                 const float* __restrict__ k,
                                                 const float* __restrict__ v,
                                                 float* __restrict__ out) {
    __shared__ float loc_s[C_ * PAD];      // fmap(k) -> local inclusive time-scan (in place)
    __shared__ float segsum[NSEG * 64];    // per-segment column sums
    __shared__ float carp[8 * 64];         // carry partials (8-way split over chunk32s)
    __shared__ float carr[64];             // cross-chunk carry per d

    float4* loc4 = (float4*)loc_s;
    float4* ca4  = (float4*)carr;

    const int bc  = blockIdx.x;            // bh*32 + c
    const int c   = bc & (NC_ - 1);
    const int bh  = bc >> 5;
    const int h   = bh & (H_ - 1);
    const int b   = bh >> 3;
    const int tid = threadIdx.x;

    const size_t base = (((size_t)b * T_ + (size_t)c * C_) * H_ + h) * D_;

    // ---- Hoist q LDGs (Phase C operands) so they fly during the scan ----
    const int t   = tid >> 3;              // 0..63 (Phase C row)
    const int dgv = tid & 7;               // 0..7  (8 d's per lane)
    const size_t rowg = base + (size_t)t * RS + dgv * 8;
    const float4 qr0 = *(const float4*)(q + rowg);
    const float4 qr1 = *(const float4*)(q + rowg + 4);

    // ---- Carry partials: 8-way split over up to 2c prior chunk32s ----
    {
        const int d = tid & 63, p = tid >> 6;    // p = 0..7
        const int pri = 2 * c;                   // prior chunk32 count
        const int lo = p * 16;
        const int hi = (pri < lo + 16) ? pri : (lo + 16);
        float run = 0.0f;
        const float* cs = &g_chunksum[(bh << 6) * D_ + d];
        #pragma unroll 4
        for (int cc = lo; cc < hi; cc++) run += cs[cc * D_];
        carp[p * 64 + d] = run;
    }

    // ---- Phase A: coalesced k -> fmap -> smem (STS.128) ----
    #pragma unroll
    for (int it = 0; it < 2; it++) {
        const int i  = tid + it * 512;         // 0..1023
        const int tt = i >> 4;
        const int dv = i & 15;
        loc4[tt * PAD4 + dv] = fmap4(*(const float4*)(k + base + (size_t)tt * RS + dv * 4));
    }
    __syncthreads();

    // ---- B1: local inclusive time-scan IN PLACE (64 d x 8 seg, 8 steps) ----
    {
        const int d = tid & 63, seg = tid >> 6;
        float run = 0.0f;
        #pragma unroll
        for (int i = 0; i < C_ / NSEG; i++) {
            const int tt = seg * (C_ / NSEG) + i;
            run += loc_s[tt * PAD + d];
            loc_s[tt * PAD + d] = run;
        }
        segsum[seg * 64 + d] = run;
    }
    __syncthreads();

    // ---- B2 offsets (segs 1..7) || carry reduce (tid<64) ----
    if (tid < 64) {
        float cr = carp[tid];
        #pragma unroll
        for (int p = 1; p < 8; p++) cr += carp[p * 64 + tid];
        carr[tid] = cr;
    } else {
        const int d = tid & 63, seg = tid >> 6;   // 1..7
        float off = segsum[d];
        for (int s = 1; s < seg; s++) off += segsum[s * 64 + d];
        #pragma unroll
        for (int i = 0; i < C_ / NSEG; i++) {
            const int tt = seg * (C_ / NSEG) + i;
            loc_s[tt * PAD + d] += off;
        }
    }
    __syncthreads();

    // ---- Phase C: 8 lanes per timestep; q already in registers ----
    {
        const float4 vv0 = *(const float4*)(v + rowg);      // issue early
        const float4 vv1 = *(const float4*)(v + rowg + 4);

        const int b4 = t * PAD4 + dgv * 2;
        float dcum = 0.0f, S = 0.0f, den = 0.0f, qs = 0.0f;
        #pragma unroll
        for (int j = 0; j < 2; j++) {
            const float4 lv = loc4[b4 + j];
            float4 pv = make_float4(0.f, 0.f, 0.f, 0.f);
            if (t > 0) pv = loc4[b4 - PAD4 + j];
            const float4 qf = (j == 0) ? fmap4(qr0) : fmap4(qr1);
            const float4 cv = ca4[dgv * 2 + j];    // warp-uniform -> broadcast

            den += qf.x * (lv.x + cv.x) + qf.y * (lv.y + cv.y)
                 + qf.z * (lv.z + cv.z) + qf.w * (lv.w + cv.w);

            dcum += lv.x - pv.x;  S += qf.x * dcum;
            dcum += lv.y - pv.y;  S += qf.y * dcum;
            dcum += lv.z - pv.z;  S += qf.z * dcum;
            dcum += lv.w - pv.w;  S += qf.w * dcum;
            qs   += qf.x + qf.y + qf.z + qf.w;
        }

        // 8-lane exclusive scan of per-group ktot across dgv
        float incl = dcum;
        #pragma unroll
        for (int o = 1; o < 8; o <<= 1) {
            float n = __shfl_up_sync(0xFFFFFFFFu, incl, o);
            if (dgv >= o) incl += n;
        }
        S += (incl - dcum) * qs;

        // butterfly-reduce S and den within the 8-lane group
        #pragma unroll
        for (int o = 4; o > 0; o >>= 1) {
            S   += __shfl_xor_sync(0xFFFFFFFFu, S, o);
            den += __shfl_xor_sync(0xFFFFFFFFu, den, o);
        }
        const float scale = S / den;

        float4 o0 = vv0, o1 = vv1;
        o0.x *= scale; o0.y *= scale; o0.z *= scale; o0.w *= scale;
        o1.x *= scale; o1.y *= scale; o1.z *= scale; o1.w *= scale;
        *(float4*)(out + rowg)     = o0;
        *(float4*)(out + rowg + 4) = o1;
    }
}

extern "C" void kernel_launch(void* const* d_in, const int* in_sizes, int n_in,
                              void* d_out, int out_size) {
    const float* q = (const float*)d_in[0];
    const float* k = (const float*)d_in[1];
    const float* v = (const float*)d_in[2];
    float* out = (float*)d_out;

    k_chunksum<<<B_ * H_ * NCS_, 256>>>(k);        // 1024 blocks
    k_main<<<B_ * H_ * NC_, 512>>>(q, k, v, out);  // 512 blocks x 512 threads
}